// round 2
// baseline (speedup 1.0000x reference)
#include <cuda_runtime.h>
#include <cuda_bf16.h>
#include <cstdint>

// Segment-sum: feat [N, 128] f32, sorted segment_ids [N] i32 -> out [G, 128] f32.
// One warp handles a contiguous row range; lane l owns columns [4l, 4l+4) as a
// float4 accumulator. Flush via atomicAdd only at segment boundaries.
// Grid sized to exactly one resident wave (148 SMs x 6 blocks @ 40 regs/256thr).

__global__ void zero_out_kernel(float4* out, int n4) {
    int i = blockIdx.x * blockDim.x + threadIdx.x;
    int stride = gridDim.x * blockDim.x;
    float4 z = make_float4(0.f, 0.f, 0.f, 0.f);
    for (; i < n4; i += stride) out[i] = z;
}

__device__ __forceinline__ void flush_acc(float* __restrict__ out, int seg, int lane,
                                          const float4& a) {
    float* p = out + (size_t)seg * 128 + lane * 4;
    atomicAdd(p + 0, a.x);
    atomicAdd(p + 1, a.y);
    atomicAdd(p + 2, a.z);
    atomicAdd(p + 3, a.w);
}

__device__ __forceinline__ void acc_add(float4& a, const float4& v) {
    a.x += v.x; a.y += v.y; a.z += v.z; a.w += v.w;
}

__global__ __launch_bounds__(256) void segsum_kernel(
    const float4* __restrict__ feat,      // [N, 32] float4
    const int* __restrict__ seg_ids,      // [N]
    float* __restrict__ out,              // [G, 128]
    int n_rows)
{
    const int lane = threadIdx.x & 31;
    const int warp = (blockIdx.x * blockDim.x + threadIdx.x) >> 5;
    const int nwarps = (gridDim.x * blockDim.x) >> 5;

    const int rows_per = (n_rows + nwarps - 1) / nwarps;
    long start = (long)warp * rows_per;
    long end = start + rows_per;
    if (end > n_rows) end = n_rows;
    if (start >= end) return;

    float4 acc = make_float4(0.f, 0.f, 0.f, 0.f);
    int cur = seg_ids[start];

    long r = start;
    // Main loop: unroll x4 with front-batched independent loads (MLP=4+).
    for (; r + 4 <= end; r += 4) {
        int s0 = seg_ids[r + 0];
        int s1 = seg_ids[r + 1];
        int s2 = seg_ids[r + 2];
        int s3 = seg_ids[r + 3];
        float4 v0 = feat[(r + 0) * 32 + lane];
        float4 v1 = feat[(r + 1) * 32 + lane];
        float4 v2 = feat[(r + 2) * 32 + lane];
        float4 v3 = feat[(r + 3) * 32 + lane];

        if (s0 != cur) { flush_acc(out, cur, lane, acc); acc = make_float4(0,0,0,0); cur = s0; }
        acc_add(acc, v0);
        if (s1 != cur) { flush_acc(out, cur, lane, acc); acc = make_float4(0,0,0,0); cur = s1; }
        acc_add(acc, v1);
        if (s2 != cur) { flush_acc(out, cur, lane, acc); acc = make_float4(0,0,0,0); cur = s2; }
        acc_add(acc, v2);
        if (s3 != cur) { flush_acc(out, cur, lane, acc); acc = make_float4(0,0,0,0); cur = s3; }
        acc_add(acc, v3);
    }
    // Tail
    for (; r < end; ++r) {
        int s = seg_ids[r];
        float4 v = feat[r * 32 + lane];
        if (s != cur) { flush_acc(out, cur, lane, acc); acc = make_float4(0,0,0,0); cur = s; }
        acc_add(acc, v);
    }
    flush_acc(out, cur, lane, acc);
}

extern "C" void kernel_launch(void* const* d_in, const int* in_sizes, int n_in,
                              void* d_out, int out_size) {
    const float4* feat = (const float4*)d_in[0];       // [N,128] f32
    const int* seg_ids = (const int*)d_in[1];          // [N] i32
    float* out = (float*)d_out;

    int n_rows = in_sizes[1];   // number of nodes

    // Zero the output (poisoned to 0xAA by harness).
    int n4 = out_size / 4;
    zero_out_kernel<<<(n4 + 255) / 256, 256>>>((float4*)d_out, n4);

    // Exactly one resident wave: 148 SMs x 6 blocks (40 regs x 256 thr = 6/SM).
    int nblocks = 148 * 6;
    segsum_kernel<<<nblocks, 256>>>(feat, seg_ids, out, n_rows);
}

// round 4
// speedup vs baseline: 1.0593x; 1.0593x over previous
#include <cuda_runtime.h>
#include <cuda_bf16.h>
#include <cstdint>

// Segment-sum: feat [N, 128] f32, sorted segment_ids [N] i32 -> out [G, 128] f32.
// One warp handles a contiguous row range; lane l owns columns [4l, 4l+4) as a
// float4 accumulator. Flush via atomicAdd only at segment boundaries.
// Unroll x8 with streaming loads to keep >= 32KB of LDG bytes in flight per SM.

__global__ void zero_out_kernel(float4* out, int n4) {
    int i = blockIdx.x * blockDim.x + threadIdx.x;
    int stride = gridDim.x * blockDim.x;
    float4 z = make_float4(0.f, 0.f, 0.f, 0.f);
    for (; i < n4; i += stride) out[i] = z;
}

__device__ __forceinline__ void flush_acc(float* __restrict__ out, int seg, int lane,
                                          const float4& a) {
    float* p = out + (size_t)seg * 128 + lane * 4;
    atomicAdd(p + 0, a.x);
    atomicAdd(p + 1, a.y);
    atomicAdd(p + 2, a.z);
    atomicAdd(p + 3, a.w);
}

__device__ __forceinline__ void acc_add(float4& a, const float4& v) {
    a.x += v.x; a.y += v.y; a.z += v.z; a.w += v.w;
}

__device__ __forceinline__ void step(float4& acc, int& cur, int s, const float4& v,
                                     float* __restrict__ out, int lane) {
    if (s != cur) {
        flush_acc(out, cur, lane, acc);
        acc = make_float4(0.f, 0.f, 0.f, 0.f);
        cur = s;
    }
    acc_add(acc, v);
}

__global__ __launch_bounds__(256, 4) void segsum_kernel(
    const float4* __restrict__ feat,      // [N, 32] float4
    const int* __restrict__ seg_ids,      // [N]
    float* __restrict__ out,              // [G, 128]
    int n_rows)
{
    const int lane = threadIdx.x & 31;
    const int warp = (blockIdx.x * blockDim.x + threadIdx.x) >> 5;
    const int nwarps = (gridDim.x * blockDim.x) >> 5;

    const int rows_per = (n_rows + nwarps - 1) / nwarps;
    long start = (long)warp * rows_per;
    long end = start + rows_per;
    if (end > n_rows) end = n_rows;
    if (start >= end) return;

    float4 acc = make_float4(0.f, 0.f, 0.f, 0.f);
    int cur = __ldg(&seg_ids[start]);

    long r = start;
    // Main loop: unroll x8, front-batched independent streaming loads.
    for (; r + 8 <= end; r += 8) {
        // ids: two vectorized loads (seg_ids addresses need only 4B align; use scalars
        // when misaligned). r*4 alignment: r is arbitrary, so load scalars via __ldg —
        // they broadcast (all lanes same address) and hit L1/L2.
        int s0 = __ldg(&seg_ids[r + 0]);
        int s1 = __ldg(&seg_ids[r + 1]);
        int s2 = __ldg(&seg_ids[r + 2]);
        int s3 = __ldg(&seg_ids[r + 3]);
        int s4 = __ldg(&seg_ids[r + 4]);
        int s5 = __ldg(&seg_ids[r + 5]);
        int s6 = __ldg(&seg_ids[r + 6]);
        int s7 = __ldg(&seg_ids[r + 7]);

        float4 v0 = __ldcs(&feat[(r + 0) * 32 + lane]);
        float4 v1 = __ldcs(&feat[(r + 1) * 32 + lane]);
        float4 v2 = __ldcs(&feat[(r + 2) * 32 + lane]);
        float4 v3 = __ldcs(&feat[(r + 3) * 32 + lane]);
        float4 v4 = __ldcs(&feat[(r + 4) * 32 + lane]);
        float4 v5 = __ldcs(&feat[(r + 5) * 32 + lane]);
        float4 v6 = __ldcs(&feat[(r + 6) * 32 + lane]);
        float4 v7 = __ldcs(&feat[(r + 7) * 32 + lane]);

        step(acc, cur, s0, v0, out, lane);
        step(acc, cur, s1, v1, out, lane);
        step(acc, cur, s2, v2, out, lane);
        step(acc, cur, s3, v3, out, lane);
        step(acc, cur, s4, v4, out, lane);
        step(acc, cur, s5, v5, out, lane);
        step(acc, cur, s6, v6, out, lane);
        step(acc, cur, s7, v7, out, lane);
    }
    // Tail
    for (; r < end; ++r) {
        int s = __ldg(&seg_ids[r]);
        float4 v = __ldcs(&feat[r * 32 + lane]);
        step(acc, cur, s, v, out, lane);
    }
    flush_acc(out, cur, lane, acc);
}

extern "C" void kernel_launch(void* const* d_in, const int* in_sizes, int n_in,
                              void* d_out, int out_size) {
    const float4* feat = (const float4*)d_in[0];       // [N,128] f32
    const int* seg_ids = (const int*)d_in[1];          // [N] i32
    float* out = (float*)d_out;

    int n_rows = in_sizes[1];   // number of nodes

    // Zero the output (poisoned to 0xAA by harness).
    int n4 = out_size / 4;
    zero_out_kernel<<<(n4 + 255) / 256, 256>>>((float4*)d_out, n4);

    // One exact wave at 4 blocks/SM (launch_bounds 256,4).
    int nblocks = 148 * 4;
    segsum_kernel<<<nblocks, 256>>>(feat, seg_ids, out, n_rows);
}